// round 1
// baseline (speedup 1.0000x reference)
#include <cuda_runtime.h>

#define THRESHOLD 0.01f
#define D 768
#define D4 (D / 4)          // 192 float4 per row
#define NTOK (8 * 2048)     // 16384 tokens

__global__ __launch_bounds__(D4)
void masked_embedding_kernel(const int* __restrict__ x,
                             const float4* __restrict__ mask,
                             const float4* __restrict__ weight,
                             float4* __restrict__ out) {
    const int token = blockIdx.x;
    const int c = threadIdx.x;                 // 0..191
    const int row = x[token];                  // broadcast load (L1/L2 hit)

    const long long src = (long long)row * D4 + c;
    const long long dst = (long long)token * D4 + c;

    float4 m = mask[src];
    float4 w = weight[src];

    float4 o;
    o.x = (m.x > THRESHOLD) ? w.x : 0.0f;
    o.y = (m.y > THRESHOLD) ? w.y : 0.0f;
    o.z = (m.z > THRESHOLD) ? w.z : 0.0f;
    o.w = (m.w > THRESHOLD) ? w.w : 0.0f;

    out[dst] = o;
}

extern "C" void kernel_launch(void* const* d_in, const int* in_sizes, int n_in,
                              void* d_out, int out_size) {
    const int*    x      = (const int*)d_in[0];
    const float4* mask   = (const float4*)d_in[1];
    const float4* weight = (const float4*)d_in[2];
    float4*       out    = (float4*)d_out;

    masked_embedding_kernel<<<NTOK, D4>>>(x, mask, weight, out);
}

// round 2
// speedup vs baseline: 1.3034x; 1.3034x over previous
#include <cuda_runtime.h>

#define THRESHOLD 0.01f
#define D 768
#define D4 (D / 4)            // 192 float4 per row
#define NTOK (8 * 2048)       // 16384 tokens
#define TPB 4                 // tokens per block

__global__ __launch_bounds__(D4)
void masked_embedding_kernel(const int* __restrict__ x,
                             const float4* __restrict__ mask,
                             const float4* __restrict__ weight,
                             float4* __restrict__ out) {
    const int token0 = blockIdx.x * TPB;
    const int c = threadIdx.x;                 // 0..191

    // Broadcast row indices for the 4 tokens of this block.
    int rows[TPB];
#pragma unroll
    for (int i = 0; i < TPB; i++)
        rows[i] = __ldg(&x[token0 + i]);

    // Front-batch all 8 independent loads (4 mask + 4 weight) before use.
    float4 m[TPB], w[TPB];
#pragma unroll
    for (int i = 0; i < TPB; i++) {
        const long long src = (long long)rows[i] * D4 + c;
        m[i] = mask[src];
        w[i] = weight[src];
    }

#pragma unroll
    for (int i = 0; i < TPB; i++) {
        float4 o;
        o.x = (m[i].x > THRESHOLD) ? w[i].x : 0.0f;
        o.y = (m[i].y > THRESHOLD) ? w[i].y : 0.0f;
        o.z = (m[i].z > THRESHOLD) ? w[i].z : 0.0f;
        o.w = (m[i].w > THRESHOLD) ? w[i].w : 0.0f;
        // Output has zero reuse: streaming store, don't pollute L2.
        __stcs(&out[(long long)(token0 + i) * D4 + c], o);
    }
}

extern "C" void kernel_launch(void* const* d_in, const int* in_sizes, int n_in,
                              void* d_out, int out_size) {
    const int*    x      = (const int*)d_in[0];
    const float4* mask   = (const float4*)d_in[1];
    const float4* weight = (const float4*)d_in[2];
    float4*       out    = (float4*)d_out;

    masked_embedding_kernel<<<NTOK / TPB, D4>>>(x, mask, weight, out);
}